// round 10
// baseline (speedup 1.0000x reference)
#include <cuda_runtime.h>
#include <cuda_bf16.h>
#include <cuda_fp16.h>
#include <cstdint>

#define BATCH 4
#define CCH 256
#define HW 4096
#define NQKV 768
#define NGROUPS 16
#define EPS 1e-5f

// ---------------- scratch ----------------
__device__ __half g_qkvt[(size_t)BATCH * HW * NQKV];      // 24 MB fp16 [n][q|k|v]
__device__ __half g_xn16[(size_t)BATCH * HW * CCH];       // 8 MB fp16 xn^T [n][c]
__device__ __half g_wq16[NQKV * CCH];                     // fp16 qkv weights
__device__ __half g_wp16[CCH * CCH];                      // fp16 proj weights
__device__ __half g_at16[(size_t)BATCH * HW * CCH];       // fp16 attn [n][c]
__device__ float g_mean[BATCH * NGROUPS];
__device__ float g_rstd[BATCH * NGROUPS];

// ---------------- helpers ----------------
__device__ __forceinline__ uint32_t smem_u32(const void* p) {
    uint32_t a;
    asm("{ .reg .u64 t; cvta.to.shared.u64 t, %1; cvt.u32.u64 %0, t; }" : "=r"(a) : "l"(p));
    return a;
}
__device__ __forceinline__ void cp16(uint32_t s, const void* g) {
    asm volatile("cp.async.cg.shared.global [%0], [%1], 16;" :: "r"(s), "l"(g) : "memory");
}
__device__ __forceinline__ void ldsm4(uint32_t& r0, uint32_t& r1, uint32_t& r2, uint32_t& r3,
                                      uint32_t a) {
    asm volatile("ldmatrix.sync.aligned.m8n8.x4.shared.b16 {%0,%1,%2,%3}, [%4];"
                 : "=r"(r0), "=r"(r1), "=r"(r2), "=r"(r3) : "r"(a));
}
__device__ __forceinline__ void ldsm4t(uint32_t& r0, uint32_t& r1, uint32_t& r2, uint32_t& r3,
                                       uint32_t a) {
    asm volatile("ldmatrix.sync.aligned.m8n8.x4.trans.shared.b16 {%0,%1,%2,%3}, [%4];"
                 : "=r"(r0), "=r"(r1), "=r"(r2), "=r"(r3) : "r"(a));
}
__device__ __forceinline__ void mma_f16(float* c, const uint32_t* a, const uint32_t* b) {
    asm volatile(
        "mma.sync.aligned.m16n8k16.row.col.f32.f16.f16.f32 "
        "{%0,%1,%2,%3}, {%4,%5,%6,%7}, {%8,%9}, {%0,%1,%2,%3};"
        : "+f"(c[0]), "+f"(c[1]), "+f"(c[2]), "+f"(c[3])
        : "r"(a[0]), "r"(a[1]), "r"(a[2]), "r"(a[3]), "r"(b[0]), "r"(b[1]));
}
#define MBAR_INIT(addr, cnt) \
    asm volatile("mbarrier.init.shared.b64 [%0], %1;" :: "r"(addr), "r"(cnt) : "memory")
#define MBAR_ARRIVE(addr) \
    asm volatile("mbarrier.arrive.shared.b64 _, [%0];" :: "r"(addr) : "memory")
#define MBAR_WAIT(addr, phase) do {                                              \
    uint32_t _m = (addr); uint32_t _p = (phase); uint32_t _d;                    \
    asm volatile("{\n\t.reg .pred P;\n\t"                                        \
        "mbarrier.try_wait.parity.acquire.cta.shared::cta.b64 P, [%1], %2;\n\t"  \
        "selp.b32 %0, 1, 0, P;\n\t}" : "=r"(_d) : "r"(_m), "r"(_p) : "memory");  \
    if (!_d) {                                                                   \
        asm volatile("{\n\t.reg .pred P1;\n\t"                                   \
        "W_%=:\n\t"                                                              \
        "mbarrier.try_wait.parity.acquire.cta.shared::cta.b64 P1, [%0], %1, 0x989680;\n\t" \
        "@P1 bra.uni D_%=;\n\tbra.uni W_%=;\n\tD_%=:\n\t}"                       \
        :: "r"(_m), "r"(_p) : "memory");                                         \
    } } while (0)

// ---------------- GroupNorm ----------------
__global__ void gn_stats(const float* __restrict__ x) {
    int bg = blockIdx.x;
    const float4* p = (const float4*)(x + (size_t)bg * 16 * HW);
    float s = 0.f, sq = 0.f;
    for (int i = threadIdx.x; i < 16384; i += 256) {
        float4 v = p[i];
        s  += v.x + v.y + v.z + v.w;
        sq += v.x*v.x + v.y*v.y + v.z*v.z + v.w*v.w;
    }
    __shared__ float ss[256], sz[256];
    ss[threadIdx.x] = s; sz[threadIdx.x] = sq;
    __syncthreads();
    for (int o = 128; o > 0; o >>= 1) {
        if (threadIdx.x < o) { ss[threadIdx.x] += ss[threadIdx.x + o]; sz[threadIdx.x] += sz[threadIdx.x + o]; }
        __syncthreads();
    }
    if (threadIdx.x == 0) {
        float m = ss[0] * (1.f / 65536.f);
        float v = sz[0] * (1.f / 65536.f) - m * m;
        g_mean[bg] = m;
        g_rstd[bg] = rsqrtf(v + EPS);
    }
}

// GroupNorm apply + transpose -> fp16 xn^T [b][n][c]
__global__ void gn_apply_t(const float* __restrict__ x, const float* __restrict__ w,
                           const float* __restrict__ bgn) {
    __shared__ float t[32][33];
    int b = blockIdx.z;
    int n0 = blockIdx.x * 32, c0 = blockIdx.y * 32;
    int tx = threadIdx.x, ty = threadIdx.y;
    const float* src = x + (size_t)b * CCH * HW;
    #pragma unroll
    for (int j = 0; j < 4; j++) {
        int c = c0 + ty + j * 8;
        int bg = b * NGROUPS + (c >> 4);
        float sc = g_rstd[bg] * w[c];
        float sh = bgn[c] - g_mean[bg] * sc;
        t[ty + j * 8][tx] = src[(size_t)c * HW + n0 + tx] * sc + sh;
    }
    __syncthreads();
    __half* d = g_xn16 + (size_t)b * HW * CCH;
    #pragma unroll
    for (int j = 0; j < 4; j++) {
        float v = t[tx][ty + j * 8];
        d[(size_t)(n0 + ty + j * 8) * CCH + c0 + tx] = __float2half_rn(v);
    }
}

// both weight tensors -> fp16 in one launch
__global__ void w16_all(const float* __restrict__ wq, const float* __restrict__ wp) {
    int i = blockIdx.x * 256 + threadIdx.x;
    if (i < NQKV * CCH) g_wq16[i] = __float2half_rn(wq[i]);
    int j = i - NQKV * CCH;
    if (j >= 0 && j < CCH * CCH) g_wp16[j] = __float2half_rn(wp[j]);
}

// ---------------- fp16 GEMM (qkv + proj variants), 4-stage cp.async pipeline ----------------
#define QK_TILE 10240
#define QK_STAGE 20480
#define QK_NST 4
#define QK_SMEM (QK_NST * QK_STAGE)

template<int EPI>
__global__ __launch_bounds__(256, 2)
void hmma_f16gemm(const __half* __restrict__ A_, const __half* __restrict__ B_,
                  const float* __restrict__ bias, __half* __restrict__ outh,
                  float* __restrict__ outf, const float* __restrict__ resid,
                  size_t aB, size_t bB, int ostr, size_t oB) {
    extern __shared__ char smem[];
    const uint32_t sb = smem_u32(smem);
    const int tid = threadIdx.x;
    const int wid = tid >> 5, lane = tid & 31;
    const int b = blockIdx.z;
    const int bm = blockIdx.y * 128;
    const int bn = blockIdx.x * 128;
    const int wm = wid & 1, wn = wid >> 1;

    const __half* A = A_ + (size_t)b * aB + (size_t)bm * CCH;
    const __half* B = B_ + (size_t)b * bB + (size_t)bn * CCH;

    const int u0row = tid >> 2, u0c = tid & 3;
    const int u1row = (tid + 256) >> 2, u1c = (tid + 256) & 3;

    float acc[4][4][4];
    #pragma unroll
    for (int mi = 0; mi < 4; mi++)
        #pragma unroll
        for (int ni = 0; ni < 4; ni++)
            #pragma unroll
            for (int r = 0; r < 4; r++) acc[mi][ni][r] = 0.f;

    const int g = lane >> 3;
    const int lrow = (g & 1) * 8 + (lane & 7);
    const int lkb  = (g >> 1) * 16;

    auto load_stage = [&](int ks) {
        const uint32_t base = sb + (ks & (QK_NST - 1)) * QK_STAGE;
        const int k0 = ks * 32;
        uint32_t so0 = base + u0row * 80 + u0c * 16;
        uint32_t so1 = base + u1row * 80 + u1c * 16;
        cp16(so0,           A + (size_t)u0row * CCH + k0 + u0c * 8);
        cp16(so1,           A + (size_t)u1row * CCH + k0 + u1c * 8);
        cp16(so0 + QK_TILE, B + (size_t)u0row * CCH + k0 + u0c * 8);
        cp16(so1 + QK_TILE, B + (size_t)u1row * CCH + k0 + u1c * 8);
    };

    const int ksteps = CCH / 32;
    #pragma unroll
    for (int s = 0; s < QK_NST - 1; s++) {
        load_stage(s);
        asm volatile("cp.async.commit_group;" ::: "memory");
    }

    for (int ks = 0; ks < ksteps; ks++) {
        asm volatile("cp.async.wait_group %0;" :: "n"(QK_NST - 2) : "memory");
        __syncthreads();
        if (ks + QK_NST - 1 < ksteps) {
            load_stage(ks + QK_NST - 1);
            asm volatile("cp.async.commit_group;" ::: "memory");
        } else {
            asm volatile("cp.async.commit_group;" ::: "memory");
        }

        const uint32_t base = sb + (ks & (QK_NST - 1)) * QK_STAGE;
        #pragma unroll
        for (int k16 = 0; k16 < 2; k16++) {
            uint32_t ah[4][4], bh[4][2];
            #pragma unroll
            for (int mi = 0; mi < 4; mi++) {
                uint32_t ra = base + (wm * 64 + mi * 16 + lrow) * 80 + k16 * 32 + lkb;
                ldsm4(ah[mi][0], ah[mi][1], ah[mi][2], ah[mi][3], ra);
            }
            #pragma unroll
            for (int p = 0; p < 2; p++) {
                uint32_t rb = base + QK_TILE + (wn * 32 + p * 16 + lrow) * 80 + k16 * 32 + lkb;
                uint32_t r0, r1, r2, r3;
                ldsm4(r0, r1, r2, r3, rb);
                bh[2*p][0] = r0; bh[2*p+1][0] = r1; bh[2*p][1] = r2; bh[2*p+1][1] = r3;
            }
            #pragma unroll
            for (int mi = 0; mi < 4; mi++)
                #pragma unroll
                for (int ni = 0; ni < 4; ni++)
                    mma_f16(acc[mi][ni], ah[mi], bh[ni]);
        }
    }

    #pragma unroll
    for (int mi = 0; mi < 4; mi++) {
        int r0 = bm + wm * 64 + mi * 16 + (lane >> 2);
        #pragma unroll
        for (int ni = 0; ni < 4; ni++) {
            int col = bn + wn * 32 + ni * 8 + (lane & 3) * 2;
            #pragma unroll
            for (int half = 0; half < 2; half++) {
                int row = r0 + half * 8;
                float v0 = acc[mi][ni][half * 2 + 0];
                float v1 = acc[mi][ni][half * 2 + 1];
                if (EPI == 0) {
                    v0 += bias[col]; v1 += bias[col + 1];
                    *(__half2*)(outh + (size_t)b * oB + (size_t)row * ostr + col) =
                        __floats2half2_rn(v0, v1);
                } else {
                    size_t o = (size_t)b * oB + (size_t)row * ostr + col;
                    float bv = bias[row];
                    float2 r = *(const float2*)(resid + o);
                    *(float2*)(outf + o) = make_float2(v0 + bv + r.x, v1 + bv + r.y);
                }
            }
        }
    }
}

// ---------------- fused flash attention: 4-stage KV ring (KB=32) ----------------
#define QR 128
#define KB 32
#define FA_NST 4
#define QSTRIDE 528
#define Q_BYTES (QR * QSTRIDE)            // 67584
#define KV_ROW 528
#define K_BYTES (KB * KV_ROW)             // 16896
#define FA_STAGE (2 * K_BYTES)            // 33792
#define FA_BAR (Q_BYTES + FA_NST * FA_STAGE)   // 202752
#define FA_SMEM (FA_BAR + 128)

__global__ __launch_bounds__(288, 1)
void flash_attn(const __half* __restrict__ qkvt) {
    extern __shared__ char smem[];
    const uint32_t sb = smem_u32(smem);
    const int tid = threadIdx.x;
    const int wid = tid >> 5, lane = tid & 31;
    const int b = blockIdx.y;
    const int bm = blockIdx.x * QR;
    const __half* base = qkvt + (size_t)b * HW * NQKV;

    const uint32_t sQ = sb;
    const uint32_t sK0 = sb + Q_BYTES;
    const uint32_t FULLB = sb + FA_BAR;        // 4 x 8B
    const uint32_t EMPTYB = sb + FA_BAR + 32;  // 4 x 8B

    if (tid == 0) {
        #pragma unroll
        for (int s = 0; s < FA_NST; s++) {
            MBAR_INIT(FULLB + s * 8, 32u);   // producer lanes (noinc)
            MBAR_INIT(EMPTYB + s * 8, 8u);   // 8 consumer warps
        }
    }
    for (int u = tid; u < 4096; u += 288) {
        int row = u >> 5, c = u & 31;
        cp16(sQ + row * QSTRIDE + c * 16, base + (size_t)(bm + row) * NQKV + c * 8);
    }
    asm volatile("cp.async.commit_group;" ::: "memory");
    asm volatile("cp.async.wait_group 0;" ::: "memory");
    __syncthreads();

    const int NITER = HW / KB;   // 128

    if (wid == 8) {
        // ---- producer warp ----
        for (int ks = 0; ks < NITER; ks++) {
            int buf = ks & (FA_NST - 1);
            if (ks >= FA_NST) {
                int par = ((ks >> 2) - 1) & 1;
                MBAR_WAIT(EMPTYB + buf * 8, par);
            }
            uint32_t st = sK0 + buf * FA_STAGE;
            const __half* gk = base + (size_t)(ks * KB) * NQKV;
            for (int u = lane; u < 1024; u += 32) {
                int row = u >> 5, c = u & 31;
                const __half* gp = gk + (size_t)row * NQKV + c * 8;
                cp16(st + row * KV_ROW + c * 16,           gp + 256);   // K
                cp16(st + K_BYTES + row * KV_ROW + c * 16, gp + 512);   // V
            }
            asm volatile("cp.async.mbarrier.arrive.noinc.shared.b64 [%0];"
                         :: "r"(FULLB + buf * 8) : "memory");
        }
        return;
    }

    // ---- consumer warps (wid 0..7; 16 Q rows each) ----
    float O[32][4];
    #pragma unroll
    for (int nt = 0; nt < 32; nt++)
        #pragma unroll
        for (int r = 0; r < 4; r++) O[nt][r] = 0.f;
    float m0 = -1e30f, m1 = -1e30f, l0 = 0.f, l1 = 0.f;

    const int g = lane >> 3;
    const int lrow = (g & 1) * 8 + (lane & 7);
    const int lkb = (g >> 1) * 16;
    const float c1 = 0.0625f * 1.44269504f;

    for (int it = 0; it < NITER; it++) {
        const int buf = it & (FA_NST - 1);
        MBAR_WAIT(FULLB + buf * 8, (it >> 2) & 1);
        const uint32_t sK = sK0 + buf * FA_STAGE;
        const uint32_t sV = sK + K_BYTES;

        // ---- S = Q K^T : warp tile 16 x 32 ----
        float S[4][4];
        #pragma unroll
        for (int nt = 0; nt < 4; nt++)
            #pragma unroll
            for (int r = 0; r < 4; r++) S[nt][r] = 0.f;

        #pragma unroll
        for (int k16 = 0; k16 < 16; k16++) {
            uint32_t a[4];
            ldsm4(a[0], a[1], a[2], a[3],
                  sQ + (wid * 16 + lrow) * QSTRIDE + k16 * 32 + lkb);
            uint32_t kb[4][2];
            #pragma unroll
            for (int p = 0; p < 2; p++) {
                uint32_t r0, r1, r2, r3;
                ldsm4(r0, r1, r2, r3, sK + (p * 16 + lrow) * KV_ROW + k16 * 32 + lkb);
                kb[2*p][0] = r0; kb[2*p+1][0] = r1;
                kb[2*p][1] = r2; kb[2*p+1][1] = r3;
            }
            #pragma unroll
            for (int nt = 0; nt < 4; nt++)
                mma_f16(S[nt], a, kb[nt]);
        }

        // ---- online softmax ----
        float mx0 = -1e30f, mx1 = -1e30f;
        #pragma unroll
        for (int nt = 0; nt < 4; nt++) {
            mx0 = fmaxf(mx0, fmaxf(S[nt][0], S[nt][1]));
            mx1 = fmaxf(mx1, fmaxf(S[nt][2], S[nt][3]));
        }
        mx0 = fmaxf(mx0, __shfl_xor_sync(0xffffffffu, mx0, 1));
        mx0 = fmaxf(mx0, __shfl_xor_sync(0xffffffffu, mx0, 2));
        mx1 = fmaxf(mx1, __shfl_xor_sync(0xffffffffu, mx1, 1));
        mx1 = fmaxf(mx1, __shfl_xor_sync(0xffffffffu, mx1, 2));
        float nm0 = fmaxf(m0, mx0), nm1 = fmaxf(m1, mx1);
        float a0 = exp2f((m0 - nm0) * c1), a1 = exp2f((m1 - nm1) * c1);
        m0 = nm0; m1 = nm1;
        float rs0 = 0.f, rs1 = 0.f;
        #pragma unroll
        for (int nt = 0; nt < 4; nt++) {
            S[nt][0] = exp2f((S[nt][0] - m0) * c1);
            S[nt][1] = exp2f((S[nt][1] - m0) * c1);
            S[nt][2] = exp2f((S[nt][2] - m1) * c1);
            S[nt][3] = exp2f((S[nt][3] - m1) * c1);
            rs0 += S[nt][0] + S[nt][1];
            rs1 += S[nt][2] + S[nt][3];
        }
        if (!__all_sync(0xffffffffu, (a0 == 1.f) && (a1 == 1.f))) {
            #pragma unroll
            for (int nt = 0; nt < 32; nt++) {
                O[nt][0] *= a0; O[nt][1] *= a0;
                O[nt][2] *= a1; O[nt][3] *= a1;
            }
            l0 *= a0; l1 *= a1;
        }
        l0 += rs0; l1 += rs1;

        // ---- O += P V (2 k16 steps of KB=32) ----
        #pragma unroll
        for (int k16 = 0; k16 < 2; k16++) {
            uint32_t pa[4];
            __half2 hh;
            hh = __floats2half2_rn(S[2*k16][0],   S[2*k16][1]);   pa[0] = *(uint32_t*)&hh;
            hh = __floats2half2_rn(S[2*k16][2],   S[2*k16][3]);   pa[1] = *(uint32_t*)&hh;
            hh = __floats2half2_rn(S[2*k16+1][0], S[2*k16+1][1]); pa[2] = *(uint32_t*)&hh;
            hh = __floats2half2_rn(S[2*k16+1][2], S[2*k16+1][3]); pa[3] = *(uint32_t*)&hh;
            int krl = k16 * 16 + (g & 1) * 8 + (lane & 7);
            #pragma unroll
            for (int p = 0; p < 16; p++) {
                int ncl = p * 16 + (g >> 1) * 8;
                uint32_t r0, r1, r2, r3;
                ldsm4t(r0, r1, r2, r3, sV + krl * KV_ROW + ncl * 2);
                uint32_t vb0[2] = {r0, r1};
                uint32_t vb1[2] = {r2, r3};
                mma_f16(O[2*p],     pa, vb0);
                mma_f16(O[2*p + 1], pa, vb1);
            }
        }
        if (lane == 0) MBAR_ARRIVE(EMPTYB + buf * 8);
    }

    // ---- epilogue: normalize -> fp16 attn ----
    l0 += __shfl_xor_sync(0xffffffffu, l0, 1);
    l0 += __shfl_xor_sync(0xffffffffu, l0, 2);
    l1 += __shfl_xor_sync(0xffffffffu, l1, 1);
    l1 += __shfl_xor_sync(0xffffffffu, l1, 2);
    float inv0 = 1.f / l0, inv1 = 1.f / l1;

    __half* oa = g_at16 + (size_t)b * HW * CCH;
    int row0 = bm + wid * 16 + (lane >> 2);
    #pragma unroll
    for (int nt = 0; nt < 32; nt++) {
        int col = nt * 8 + (lane & 3) * 2;
        *(__half2*)(oa + (size_t)row0 * CCH + col) =
            __floats2half2_rn(O[nt][0] * inv0, O[nt][1] * inv0);
        *(__half2*)(oa + (size_t)(row0 + 8) * CCH + col) =
            __floats2half2_rn(O[nt][2] * inv1, O[nt][3] * inv1);
    }
}

// ---------------- launch ----------------
extern "C" void kernel_launch(void* const* d_in, const int* in_sizes, int n_in,
                              void* d_out, int out_size) {
    const float* x     = (const float*)d_in[0];
    const float* gnw   = (const float*)d_in[1];
    const float* gnb   = (const float*)d_in[2];
    const float* qkvw  = (const float*)d_in[3];
    const float* qkvb  = (const float*)d_in[4];
    const float* projw = (const float*)d_in[5];
    const float* projb = (const float*)d_in[6];
    float* out = (float*)d_out;

    __half *qkvt, *xn16, *wq16, *wp16, *at16;
    cudaGetSymbolAddress((void**)&qkvt, g_qkvt);
    cudaGetSymbolAddress((void**)&xn16, g_xn16);
    cudaGetSymbolAddress((void**)&wq16, g_wq16);
    cudaGetSymbolAddress((void**)&wp16, g_wp16);
    cudaGetSymbolAddress((void**)&at16, g_at16);

    cudaFuncSetAttribute((const void*)hmma_f16gemm<0>,
                         cudaFuncAttributeMaxDynamicSharedMemorySize, QK_SMEM);
    cudaFuncSetAttribute((const void*)hmma_f16gemm<1>,
                         cudaFuncAttributeMaxDynamicSharedMemorySize, QK_SMEM);
    cudaFuncSetAttribute((const void*)flash_attn,
                         cudaFuncAttributeMaxDynamicSharedMemorySize, FA_SMEM);

    // 1. GroupNorm -> fp16 xn^T
    gn_stats<<<BATCH * NGROUPS, 256>>>(x);
    gn_apply_t<<<dim3(HW / 32, CCH / 32, BATCH), dim3(32, 8)>>>(x, gnw, gnb);

    // 2. weight conversions (one launch)
    w16_all<<<(NQKV * CCH + CCH * CCH + 255) / 256, 256>>>(qkvw, projw);

    // 3. qkv fp16 GEMM
    hmma_f16gemm<0><<<dim3(NQKV / 128, HW / 128, BATCH), 256, QK_SMEM>>>(
        xn16, wq16, qkvb, qkvt, nullptr, nullptr,
        (size_t)HW * CCH, 0, NQKV, (size_t)HW * NQKV);

    // 4-6. fused flash attention (4-stage ring)
    flash_attn<<<dim3(HW / QR, BATCH), 288, FA_SMEM>>>(qkvt);

    // 7. proj fp16
    hmma_f16gemm<1><<<dim3(HW / 128, CCH / 128, BATCH), 256, QK_SMEM>>>(
        wp16, at16, projb, nullptr, out, x,
        0, (size_t)HW * CCH, HW, (size_t)CCH * HW);
}

// round 11
// speedup vs baseline: 1.4292x; 1.4292x over previous
#include <cuda_runtime.h>
#include <cuda_bf16.h>
#include <cuda_fp16.h>
#include <cstdint>

#define BATCH 4
#define CCH 256
#define HW 4096
#define NQKV 768
#define NGROUPS 16
#define EPS 1e-5f

// ---------------- scratch ----------------
__device__ __half g_qkvt[(size_t)BATCH * HW * NQKV];      // 24 MB fp16 [n][q|k|v]
__device__ __half g_xn16[(size_t)BATCH * HW * CCH];       // 8 MB fp16 xn^T [n][c]
__device__ __half g_wq16[NQKV * CCH];                     // fp16 qkv weights
__device__ __half g_wp16[CCH * CCH];                      // fp16 proj weights
__device__ __half g_at16[(size_t)BATCH * HW * CCH];       // fp16 attn [n][c]
__device__ float g_mean[BATCH * NGROUPS];
__device__ float g_rstd[BATCH * NGROUPS];

// ---------------- helpers ----------------
__device__ __forceinline__ uint32_t smem_u32(const void* p) {
    uint32_t a;
    asm("{ .reg .u64 t; cvta.to.shared.u64 t, %1; cvt.u32.u64 %0, t; }" : "=r"(a) : "l"(p));
    return a;
}
__device__ __forceinline__ void cp16(uint32_t s, const void* g) {
    asm volatile("cp.async.cg.shared.global [%0], [%1], 16;" :: "r"(s), "l"(g) : "memory");
}
__device__ __forceinline__ void ldsm4(uint32_t& r0, uint32_t& r1, uint32_t& r2, uint32_t& r3,
                                      uint32_t a) {
    asm volatile("ldmatrix.sync.aligned.m8n8.x4.shared.b16 {%0,%1,%2,%3}, [%4];"
                 : "=r"(r0), "=r"(r1), "=r"(r2), "=r"(r3) : "r"(a));
}
__device__ __forceinline__ void ldsm4t(uint32_t& r0, uint32_t& r1, uint32_t& r2, uint32_t& r3,
                                       uint32_t a) {
    asm volatile("ldmatrix.sync.aligned.m8n8.x4.trans.shared.b16 {%0,%1,%2,%3}, [%4];"
                 : "=r"(r0), "=r"(r1), "=r"(r2), "=r"(r3) : "r"(a));
}
__device__ __forceinline__ void mma_f16(float* c, const uint32_t* a, const uint32_t* b) {
    asm volatile(
        "mma.sync.aligned.m16n8k16.row.col.f32.f16.f16.f32 "
        "{%0,%1,%2,%3}, {%4,%5,%6,%7}, {%8,%9}, {%0,%1,%2,%3};"
        : "+f"(c[0]), "+f"(c[1]), "+f"(c[2]), "+f"(c[3])
        : "r"(a[0]), "r"(a[1]), "r"(a[2]), "r"(a[3]), "r"(b[0]), "r"(b[1]));
}
#define MBAR_INIT(addr, cnt) \
    asm volatile("mbarrier.init.shared.b64 [%0], %1;" :: "r"(addr), "r"(cnt) : "memory")
#define MBAR_ARRIVE(addr) \
    asm volatile("mbarrier.arrive.shared.b64 _, [%0];" :: "r"(addr) : "memory")
#define MBAR_WAIT(addr, phase) do {                                              \
    uint32_t _m = (addr); uint32_t _p = (phase); uint32_t _d;                    \
    asm volatile("{\n\t.reg .pred P;\n\t"                                        \
        "mbarrier.try_wait.parity.acquire.cta.shared::cta.b64 P, [%1], %2;\n\t"  \
        "selp.b32 %0, 1, 0, P;\n\t}" : "=r"(_d) : "r"(_m), "r"(_p) : "memory");  \
    if (!_d) {                                                                   \
        asm volatile("{\n\t.reg .pred P1;\n\t"                                   \
        "W_%=:\n\t"                                                              \
        "mbarrier.try_wait.parity.acquire.cta.shared::cta.b64 P1, [%0], %1, 0x989680;\n\t" \
        "@P1 bra.uni D_%=;\n\tbra.uni W_%=;\n\tD_%=:\n\t}"                       \
        :: "r"(_m), "r"(_p) : "memory");                                         \
    } } while (0)

// ---------------- GroupNorm ----------------
__global__ void gn_stats(const float* __restrict__ x) {
    int bg = blockIdx.x;
    const float4* p = (const float4*)(x + (size_t)bg * 16 * HW);
    float s = 0.f, sq = 0.f;
    for (int i = threadIdx.x; i < 16384; i += 256) {
        float4 v = p[i];
        s  += v.x + v.y + v.z + v.w;
        sq += v.x*v.x + v.y*v.y + v.z*v.z + v.w*v.w;
    }
    __shared__ float ss[256], sz[256];
    ss[threadIdx.x] = s; sz[threadIdx.x] = sq;
    __syncthreads();
    for (int o = 128; o > 0; o >>= 1) {
        if (threadIdx.x < o) { ss[threadIdx.x] += ss[threadIdx.x + o]; sz[threadIdx.x] += sz[threadIdx.x + o]; }
        __syncthreads();
    }
    if (threadIdx.x == 0) {
        float m = ss[0] * (1.f / 65536.f);
        float v = sz[0] * (1.f / 65536.f) - m * m;
        g_mean[bg] = m;
        g_rstd[bg] = rsqrtf(v + EPS);
    }
}

// GroupNorm apply + transpose -> fp16 xn^T [b][n][c]
__global__ void gn_apply_t(const float* __restrict__ x, const float* __restrict__ w,
                           const float* __restrict__ bgn) {
    __shared__ float t[32][33];
    int b = blockIdx.z;
    int n0 = blockIdx.x * 32, c0 = blockIdx.y * 32;
    int tx = threadIdx.x, ty = threadIdx.y;
    const float* src = x + (size_t)b * CCH * HW;
    #pragma unroll
    for (int j = 0; j < 4; j++) {
        int c = c0 + ty + j * 8;
        int bg = b * NGROUPS + (c >> 4);
        float sc = g_rstd[bg] * w[c];
        float sh = bgn[c] - g_mean[bg] * sc;
        t[ty + j * 8][tx] = src[(size_t)c * HW + n0 + tx] * sc + sh;
    }
    __syncthreads();
    __half* d = g_xn16 + (size_t)b * HW * CCH;
    #pragma unroll
    for (int j = 0; j < 4; j++) {
        float v = t[tx][ty + j * 8];
        d[(size_t)(n0 + ty + j * 8) * CCH + c0 + tx] = __float2half_rn(v);
    }
}

// both weight tensors -> fp16 in one launch
__global__ void w16_all(const float* __restrict__ wq, const float* __restrict__ wp) {
    int i = blockIdx.x * 256 + threadIdx.x;
    if (i < NQKV * CCH) g_wq16[i] = __float2half_rn(wq[i]);
    int j = i - NQKV * CCH;
    if (j >= 0 && j < CCH * CCH) g_wp16[j] = __float2half_rn(wp[j]);
}

// ---------------- fp16 GEMM (qkv + proj), K-chunk 64, double-buffered ----------------
// C[m][n] over A[m][K], B[n][K], K=256 (4 ksteps of 64). 128x128 tile.
// EPI 0 (qkv): A=tokens (batched), B=weights; out fp16, bias[col].
// EPI 1 (proj): A=weights, B=attn tokens (batched); outf fp32 = acc + bias[row] + resid.
#define GT_ROW 144
#define GT_TILE (128 * GT_ROW)       // 18432
#define GT_STAGE (2 * GT_TILE)       // 36864
#define GT_SMEM (2 * GT_STAGE)       // 73728

template<int EPI>
__global__ __launch_bounds__(256, 2)
void hmma_f16gemm(const __half* __restrict__ A_, const __half* __restrict__ B_,
                  const float* __restrict__ bias, __half* __restrict__ outh,
                  float* __restrict__ outf, const float* __restrict__ resid,
                  size_t aB, size_t bB, int ostr, size_t oB) {
    extern __shared__ char smem[];
    const uint32_t sb = smem_u32(smem);
    const int tid = threadIdx.x;
    const int wid = tid >> 5, lane = tid & 31;
    const int b = blockIdx.z;
    const int bm = blockIdx.y * 128;
    const int bn = blockIdx.x * 128;
    const int wm = wid & 1, wn = wid >> 1;

    const __half* A = A_ + (size_t)b * aB + (size_t)bm * CCH;
    const __half* B = B_ + (size_t)b * bB + (size_t)bn * CCH;

    float acc[4][4][4];
    #pragma unroll
    for (int mi = 0; mi < 4; mi++)
        #pragma unroll
        for (int ni = 0; ni < 4; ni++)
            #pragma unroll
            for (int r = 0; r < 4; r++) acc[mi][ni][r] = 0.f;

    const int g = lane >> 3;
    const int lrow = (g & 1) * 8 + (lane & 7);
    const int lkb  = (g >> 1) * 16;

    // per-thread load coords: 8 chunks per 128x64 tile (1024 chunks / 256 threads... 4 each)
    auto load_stage = [&](int ks, int buf) {
        const uint32_t base = sb + buf * GT_STAGE;
        const int k0 = ks * 64;
        #pragma unroll
        for (int u = 0; u < 4; u++) {
            int idx = tid + u * 256;            // 0..1023
            int row = idx >> 3, c = idx & 7;
            uint32_t so = base + row * GT_ROW + c * 16;
            size_t go = (size_t)row * CCH + k0 + c * 8;
            cp16(so,           A + go);
            cp16(so + GT_TILE, B + go);
        }
    };

    load_stage(0, 0);
    asm volatile("cp.async.commit_group;" ::: "memory");

    const int ksteps = CCH / 64;   // 4
    for (int ks = 0; ks < ksteps; ks++) {
        const int buf = ks & 1;
        if (ks + 1 < ksteps) {
            load_stage(ks + 1, buf ^ 1);
            asm volatile("cp.async.commit_group;" ::: "memory");
            asm volatile("cp.async.wait_group 1;" ::: "memory");
        } else {
            asm volatile("cp.async.wait_group 0;" ::: "memory");
        }
        __syncthreads();

        const uint32_t base = sb + buf * GT_STAGE;
        #pragma unroll
        for (int k16 = 0; k16 < 4; k16++) {
            uint32_t ah[4][4], bh[4][2];
            #pragma unroll
            for (int mi = 0; mi < 4; mi++) {
                uint32_t ra = base + (wm * 64 + mi * 16 + lrow) * GT_ROW + k16 * 32 + lkb;
                ldsm4(ah[mi][0], ah[mi][1], ah[mi][2], ah[mi][3], ra);
            }
            #pragma unroll
            for (int p = 0; p < 2; p++) {
                uint32_t rb = base + GT_TILE + (wn * 32 + p * 16 + lrow) * GT_ROW + k16 * 32 + lkb;
                uint32_t r0, r1, r2, r3;
                ldsm4(r0, r1, r2, r3, rb);
                bh[2*p][0] = r0; bh[2*p+1][0] = r1; bh[2*p][1] = r2; bh[2*p+1][1] = r3;
            }
            #pragma unroll
            for (int mi = 0; mi < 4; mi++)
                #pragma unroll
                for (int ni = 0; ni < 4; ni++)
                    mma_f16(acc[mi][ni], ah[mi], bh[ni]);
        }
        __syncthreads();
    }

    #pragma unroll
    for (int mi = 0; mi < 4; mi++) {
        int r0 = bm + wm * 64 + mi * 16 + (lane >> 2);
        #pragma unroll
        for (int ni = 0; ni < 4; ni++) {
            int col = bn + wn * 32 + ni * 8 + (lane & 3) * 2;
            #pragma unroll
            for (int half = 0; half < 2; half++) {
                int row = r0 + half * 8;
                float v0 = acc[mi][ni][half * 2 + 0];
                float v1 = acc[mi][ni][half * 2 + 1];
                if (EPI == 0) {
                    v0 += bias[col]; v1 += bias[col + 1];
                    *(__half2*)(outh + (size_t)b * oB + (size_t)row * ostr + col) =
                        __floats2half2_rn(v0, v1);
                } else {
                    size_t o = (size_t)b * oB + (size_t)row * ostr + col;
                    float bv = bias[row];
                    float2 r = *(const float2*)(resid + o);
                    *(float2*)(outf + o) = make_float2(v0 + bv + r.x, v1 + bv + r.y);
                }
            }
        }
    }
}

// ---------------- fused flash attention (R8 config: KB=64, 2-stage, producer warp) ----------------
#define QR 128
#define KB 64
#define QSTRIDE 528
#define Q_BYTES (QR * QSTRIDE)            // 67584
#define KV_ROW 528
#define K_BYTES (KB * KV_ROW)             // 33792
#define FA_STAGE (2 * K_BYTES)            // 67584
#define FA_BAR (Q_BYTES + 2 * FA_STAGE)   // 202752
#define FA_SMEM (FA_BAR + 64)

__global__ __launch_bounds__(288, 1)
void flash_attn(const __half* __restrict__ qkvt) {
    extern __shared__ char smem[];
    const uint32_t sb = smem_u32(smem);
    const int tid = threadIdx.x;
    const int wid = tid >> 5, lane = tid & 31;
    const int b = blockIdx.y;
    const int bm = blockIdx.x * QR;
    const __half* base = qkvt + (size_t)b * HW * NQKV;

    const uint32_t sQ = sb;
    const uint32_t sK0 = sb + Q_BYTES;
    const uint32_t BARS = sb + FA_BAR;   // full0 +0, full1 +8, empty0 +16, empty1 +24

    if (tid == 0) {
        MBAR_INIT(BARS + 0, 32u);
        MBAR_INIT(BARS + 8, 32u);
        MBAR_INIT(BARS + 16, 8u);
        MBAR_INIT(BARS + 24, 8u);
    }
    for (int u = tid; u < 4096; u += 288) {
        int row = u >> 5, c = u & 31;
        cp16(sQ + row * QSTRIDE + c * 16, base + (size_t)(bm + row) * NQKV + c * 8);
    }
    asm volatile("cp.async.commit_group;" ::: "memory");
    asm volatile("cp.async.wait_group 0;" ::: "memory");
    __syncthreads();

    const int NITER = HW / KB;

    if (wid == 8) {
        for (int ks = 0; ks < NITER; ks++) {
            int buf = ks & 1;
            if (ks >= 2) {
                int par = ((ks >> 1) - 1) & 1;
                MBAR_WAIT(BARS + 16 + buf * 8, par);
            }
            uint32_t st = sK0 + buf * FA_STAGE;
            const __half* gk = base + (size_t)(ks * KB) * NQKV;
            for (int u = lane; u < 2048; u += 32) {
                int row = u >> 5, c = u & 31;
                const __half* gp = gk + (size_t)row * NQKV + c * 8;
                cp16(st + row * KV_ROW + c * 16,           gp + 256);   // K
                cp16(st + K_BYTES + row * KV_ROW + c * 16, gp + 512);   // V
            }
            asm volatile("cp.async.mbarrier.arrive.noinc.shared.b64 [%0];"
                         :: "r"(BARS + buf * 8) : "memory");
        }
        return;
    }

    float O[32][4];
    #pragma unroll
    for (int nt = 0; nt < 32; nt++)
        #pragma unroll
        for (int r = 0; r < 4; r++) O[nt][r] = 0.f;
    float m0 = -1e30f, m1 = -1e30f, l0 = 0.f, l1 = 0.f;

    const int g = lane >> 3;
    const int lrow = (g & 1) * 8 + (lane & 7);
    const int lkb = (g >> 1) * 16;
    const float c1 = 0.0625f * 1.44269504f;

    for (int it = 0; it < NITER; it++) {
        const int buf = it & 1;
        MBAR_WAIT(BARS + buf * 8, (it >> 1) & 1);
        const uint32_t sK = sK0 + buf * FA_STAGE;
        const uint32_t sV = sK + K_BYTES;

        float S[8][4];
        #pragma unroll
        for (int nt = 0; nt < 8; nt++)
            #pragma unroll
            for (int r = 0; r < 4; r++) S[nt][r] = 0.f;

        #pragma unroll
        for (int k16 = 0; k16 < 16; k16++) {
            uint32_t a[4];
            ldsm4(a[0], a[1], a[2], a[3],
                  sQ + (wid * 16 + lrow) * QSTRIDE + k16 * 32 + lkb);
            uint32_t kb[8][2];
            #pragma unroll
            for (int p = 0; p < 4; p++) {
                uint32_t r0, r1, r2, r3;
                ldsm4(r0, r1, r2, r3, sK + (p * 16 + lrow) * KV_ROW + k16 * 32 + lkb);
                kb[2*p][0] = r0; kb[2*p+1][0] = r1;
                kb[2*p][1] = r2; kb[2*p+1][1] = r3;
            }
            #pragma unroll
            for (int nt = 0; nt < 8; nt++)
                mma_f16(S[nt], a, kb[nt]);
        }

        float mx0 = -1e30f, mx1 = -1e30f;
        #pragma unroll
        for (int nt = 0; nt < 8; nt++) {
            mx0 = fmaxf(mx0, fmaxf(S[nt][0], S[nt][1]));
            mx1 = fmaxf(mx1, fmaxf(S[nt][2], S[nt][3]));
        }
        mx0 = fmaxf(mx0, __shfl_xor_sync(0xffffffffu, mx0, 1));
        mx0 = fmaxf(mx0, __shfl_xor_sync(0xffffffffu, mx0, 2));
        mx1 = fmaxf(mx1, __shfl_xor_sync(0xffffffffu, mx1, 1));
        mx1 = fmaxf(mx1, __shfl_xor_sync(0xffffffffu, mx1, 2));
        float nm0 = fmaxf(m0, mx0), nm1 = fmaxf(m1, mx1);
        float a0 = exp2f((m0 - nm0) * c1), a1 = exp2f((m1 - nm1) * c1);
        m0 = nm0; m1 = nm1;
        float rs0 = 0.f, rs1 = 0.f;
        #pragma unroll
        for (int nt = 0; nt < 8; nt++) {
            S[nt][0] = exp2f((S[nt][0] - m0) * c1);
            S[nt][1] = exp2f((S[nt][1] - m0) * c1);
            S[nt][2] = exp2f((S[nt][2] - m1) * c1);
            S[nt][3] = exp2f((S[nt][3] - m1) * c1);
            rs0 += S[nt][0] + S[nt][1];
            rs1 += S[nt][2] + S[nt][3];
        }
        if (!__all_sync(0xffffffffu, (a0 == 1.f) && (a1 == 1.f))) {
            #pragma unroll
            for (int nt = 0; nt < 32; nt++) {
                O[nt][0] *= a0; O[nt][1] *= a0;
                O[nt][2] *= a1; O[nt][3] *= a1;
            }
            l0 *= a0; l1 *= a1;
        }
        l0 += rs0; l1 += rs1;

        #pragma unroll
        for (int k16 = 0; k16 < 4; k16++) {
            uint32_t pa[4];
            __half2 hh;
            hh = __floats2half2_rn(S[2*k16][0],   S[2*k16][1]);   pa[0] = *(uint32_t*)&hh;
            hh = __floats2half2_rn(S[2*k16][2],   S[2*k16][3]);   pa[1] = *(uint32_t*)&hh;
            hh = __floats2half2_rn(S[2*k16+1][0], S[2*k16+1][1]); pa[2] = *(uint32_t*)&hh;
            hh = __floats2half2_rn(S[2*k16+1][2], S[2*k16+1][3]); pa[3] = *(uint32_t*)&hh;
            int krl = k16 * 16 + (g & 1) * 8 + (lane & 7);
            #pragma unroll
            for (int p = 0; p < 16; p++) {
                int ncl = p * 16 + (g >> 1) * 8;
                uint32_t r0, r1, r2, r3;
                ldsm4t(r0, r1, r2, r3, sV + krl * KV_ROW + ncl * 2);
                uint32_t vb0[2] = {r0, r1};
                uint32_t vb1[2] = {r2, r3};
                mma_f16(O[2*p],     pa, vb0);
                mma_f16(O[2*p + 1], pa, vb1);
            }
        }
        if (lane == 0) MBAR_ARRIVE(BARS + 16 + buf * 8);
    }

    // ---- epilogue: normalize -> fp16 attn ----
    l0 += __shfl_xor_sync(0xffffffffu, l0, 1);
    l0 += __shfl_xor_sync(0xffffffffu, l0, 2);
    l1 += __shfl_xor_sync(0xffffffffu, l1, 1);
    l1 += __shfl_xor_sync(0xffffffffu, l1, 2);
    float inv0 = 1.f / l0, inv1 = 1.f / l1;

    __half* oa = g_at16 + (size_t)b * HW * CCH;
    int row0 = bm + wid * 16 + (lane >> 2);
    #pragma unroll
    for (int nt = 0; nt < 32; nt++) {
        int col = nt * 8 + (lane & 3) * 2;
        *(__half2*)(oa + (size_t)row0 * CCH + col) =
            __floats2half2_rn(O[nt][0] * inv0, O[nt][1] * inv0);
        *(__half2*)(oa + (size_t)(row0 + 8) * CCH + col) =
            __floats2half2_rn(O[nt][2] * inv1, O[nt][3] * inv1);
    }
}

// ---------------- launch ----------------
extern "C" void kernel_launch(void* const* d_in, const int* in_sizes, int n_in,
                              void* d_out, int out_size) {
    const float* x     = (const float*)d_in[0];
    const float* gnw   = (const float*)d_in[1];
    const float* gnb   = (const float*)d_in[2];
    const float* qkvw  = (const float*)d_in[3];
    const float* qkvb  = (const float*)d_in[4];
    const float* projw = (const float*)d_in[5];
    const float* projb = (const float*)d_in[6];
    float* out = (float*)d_out;

    __half *qkvt, *xn16, *wq16, *wp16, *at16;
    cudaGetSymbolAddress((void**)&qkvt, g_qkvt);
    cudaGetSymbolAddress((void**)&xn16, g_xn16);
    cudaGetSymbolAddress((void**)&wq16, g_wq16);
    cudaGetSymbolAddress((void**)&wp16, g_wp16);
    cudaGetSymbolAddress((void**)&at16, g_at16);

    cudaFuncSetAttribute((const void*)hmma_f16gemm<0>,
                         cudaFuncAttributeMaxDynamicSharedMemorySize, GT_SMEM);
    cudaFuncSetAttribute((const void*)hmma_f16gemm<1>,
                         cudaFuncAttributeMaxDynamicSharedMemorySize, GT_SMEM);
    cudaFuncSetAttribute((const void*)flash_attn,
                         cudaFuncAttributeMaxDynamicSharedMemorySize, FA_SMEM);

    // 1. GroupNorm -> fp16 xn^T
    gn_stats<<<BATCH * NGROUPS, 256>>>(x);
    gn_apply_t<<<dim3(HW / 32, CCH / 32, BATCH), dim3(32, 8)>>>(x, gnw, gnb);

    // 2. weight conversions (one launch)
    w16_all<<<(NQKV * CCH + CCH * CCH + 255) / 256, 256>>>(qkvw, projw);

    // 3. qkv fp16 GEMM
    hmma_f16gemm<0><<<dim3(NQKV / 128, HW / 128, BATCH), 256, GT_SMEM>>>(
        xn16, wq16, qkvb, qkvt, nullptr, nullptr,
        (size_t)HW * CCH, 0, NQKV, (size_t)HW * NQKV);

    // 4-6. fused flash attention (KB=64, 2-stage — best-known config)
    flash_attn<<<dim3(HW / QR, BATCH), 288, FA_SMEM>>>(qkvt);

    // 7. proj fp16
    hmma_f16gemm<1><<<dim3(HW / 128, CCH / 128, BATCH), 256, GT_SMEM>>>(
        wp16, at16, projb, nullptr, out, x,
        0, (size_t)HW * CCH, HW, (size_t)CCH * HW);
}

// round 12
// speedup vs baseline: 1.5778x; 1.1039x over previous
#include <cuda_runtime.h>
#include <cuda_bf16.h>
#include <cuda_fp16.h>
#include <cstdint>

#define BATCH 4
#define CCH 256
#define HW 4096
#define NQKV 768
#define NGROUPS 16
#define EPS 1e-5f

// ---------------- scratch ----------------
__device__ __half g_qkvt[(size_t)BATCH * HW * NQKV];      // 24 MB fp16 [n][q|k|v]
__device__ __half g_xn16[(size_t)BATCH * HW * CCH];       // 8 MB fp16 xn^T [n][c]
__device__ __half g_wq16[NQKV * CCH];                     // fp16 qkv weights
__device__ __half g_wp16[CCH * CCH];                      // fp16 proj weights
__device__ __half g_at16[(size_t)BATCH * HW * CCH];       // fp16 attn [n][c]
__device__ float g_mean[BATCH * NGROUPS];
__device__ float g_rstd[BATCH * NGROUPS];

// ---------------- helpers ----------------
__device__ __forceinline__ uint32_t smem_u32(const void* p) {
    uint32_t a;
    asm("{ .reg .u64 t; cvta.to.shared.u64 t, %1; cvt.u32.u64 %0, t; }" : "=r"(a) : "l"(p));
    return a;
}
__device__ __forceinline__ void cp16(uint32_t s, const void* g) {
    asm volatile("cp.async.cg.shared.global [%0], [%1], 16;" :: "r"(s), "l"(g) : "memory");
}
__device__ __forceinline__ void ldsm4(uint32_t& r0, uint32_t& r1, uint32_t& r2, uint32_t& r3,
                                      uint32_t a) {
    asm volatile("ldmatrix.sync.aligned.m8n8.x4.shared.b16 {%0,%1,%2,%3}, [%4];"
                 : "=r"(r0), "=r"(r1), "=r"(r2), "=r"(r3) : "r"(a));
}
__device__ __forceinline__ void ldsm4t(uint32_t& r0, uint32_t& r1, uint32_t& r2, uint32_t& r3,
                                       uint32_t a) {
    asm volatile("ldmatrix.sync.aligned.m8n8.x4.trans.shared.b16 {%0,%1,%2,%3}, [%4];"
                 : "=r"(r0), "=r"(r1), "=r"(r2), "=r"(r3) : "r"(a));
}
__device__ __forceinline__ void mma_f16(float* c, const uint32_t* a, const uint32_t* b) {
    asm volatile(
        "mma.sync.aligned.m16n8k16.row.col.f32.f16.f16.f32 "
        "{%0,%1,%2,%3}, {%4,%5,%6,%7}, {%8,%9}, {%0,%1,%2,%3};"
        : "+f"(c[0]), "+f"(c[1]), "+f"(c[2]), "+f"(c[3])
        : "r"(a[0]), "r"(a[1]), "r"(a[2]), "r"(a[3]), "r"(b[0]), "r"(b[1]));
}
#define MBAR_INIT(addr, cnt) \
    asm volatile("mbarrier.init.shared.b64 [%0], %1;" :: "r"(addr), "r"(cnt) : "memory")
#define MBAR_ARRIVE(addr) \
    asm volatile("mbarrier.arrive.shared.b64 _, [%0];" :: "r"(addr) : "memory")
#define MBAR_WAIT(addr, phase) do {                                              \
    uint32_t _m = (addr); uint32_t _p = (phase); uint32_t _d;                    \
    asm volatile("{\n\t.reg .pred P;\n\t"                                        \
        "mbarrier.try_wait.parity.acquire.cta.shared::cta.b64 P, [%1], %2;\n\t"  \
        "selp.b32 %0, 1, 0, P;\n\t}" : "=r"(_d) : "r"(_m), "r"(_p) : "memory");  \
    if (!_d) {                                                                   \
        asm volatile("{\n\t.reg .pred P1;\n\t"                                   \
        "W_%=:\n\t"                                                              \
        "mbarrier.try_wait.parity.acquire.cta.shared::cta.b64 P1, [%0], %1, 0x989680;\n\t" \
        "@P1 bra.uni D_%=;\n\tbra.uni W_%=;\n\tD_%=:\n\t}"                       \
        :: "r"(_m), "r"(_p) : "memory");                                         \
    } } while (0)

// ---------------- GroupNorm stats + weight conversion (fused launch) ----------------
__global__ void gn_stats_w16(const float* __restrict__ x, const float* __restrict__ wq,
                             const float* __restrict__ wp) {
    if (blockIdx.x >= BATCH * NGROUPS) {
        // weight conversion blocks
        int i = (blockIdx.x - BATCH * NGROUPS) * 256 + threadIdx.x;
        if (i < NQKV * CCH) g_wq16[i] = __float2half_rn(wq[i]);
        int j = i - NQKV * CCH;
        if (j >= 0 && j < CCH * CCH) g_wp16[j] = __float2half_rn(wp[j]);
        return;
    }
    int bg = blockIdx.x;
    const float4* p = (const float4*)(x + (size_t)bg * 16 * HW);
    float s = 0.f, sq = 0.f;
    for (int i = threadIdx.x; i < 16384; i += 256) {
        float4 v = p[i];
        s  += v.x + v.y + v.z + v.w;
        sq += v.x*v.x + v.y*v.y + v.z*v.z + v.w*v.w;
    }
    __shared__ float ss[256], sz[256];
    ss[threadIdx.x] = s; sz[threadIdx.x] = sq;
    __syncthreads();
    for (int o = 128; o > 0; o >>= 1) {
        if (threadIdx.x < o) { ss[threadIdx.x] += ss[threadIdx.x + o]; sz[threadIdx.x] += sz[threadIdx.x + o]; }
        __syncthreads();
    }
    if (threadIdx.x == 0) {
        float m = ss[0] * (1.f / 65536.f);
        float v = sz[0] * (1.f / 65536.f) - m * m;
        g_mean[bg] = m;
        g_rstd[bg] = rsqrtf(v + EPS);
    }
}

// GroupNorm apply + transpose -> fp16 xn^T [b][n][c]
__global__ void gn_apply_t(const float* __restrict__ x, const float* __restrict__ w,
                           const float* __restrict__ bgn) {
    __shared__ float t[32][33];
    int b = blockIdx.z;
    int n0 = blockIdx.x * 32, c0 = blockIdx.y * 32;
    int tx = threadIdx.x, ty = threadIdx.y;
    const float* src = x + (size_t)b * CCH * HW;
    #pragma unroll
    for (int j = 0; j < 4; j++) {
        int c = c0 + ty + j * 8;
        int bg = b * NGROUPS + (c >> 4);
        float sc = g_rstd[bg] * w[c];
        float sh = bgn[c] - g_mean[bg] * sc;
        t[ty + j * 8][tx] = src[(size_t)c * HW + n0 + tx] * sc + sh;
    }
    __syncthreads();
    __half* d = g_xn16 + (size_t)b * HW * CCH;
    #pragma unroll
    for (int j = 0; j < 4; j++) {
        float v = t[tx][ty + j * 8];
        d[(size_t)(n0 + ty + j * 8) * CCH + c0 + tx] = __float2half_rn(v);
    }
}

// ---------------- fp16 GEMM (qkv + proj), K-chunk 64, double-buffered ----------------
#define GT_ROW 144
#define GT_TILE (128 * GT_ROW)       // 18432
#define GT_STAGE (2 * GT_TILE)       // 36864
#define GT_SMEM (2 * GT_STAGE)       // 73728

template<int EPI>
__global__ __launch_bounds__(256, 2)
void hmma_f16gemm(const __half* __restrict__ A_, const __half* __restrict__ B_,
                  const float* __restrict__ bias, __half* __restrict__ outh,
                  float* __restrict__ outf, const float* __restrict__ resid,
                  size_t aB, size_t bB, int ostr, size_t oB) {
    extern __shared__ char smem[];
    const uint32_t sb = smem_u32(smem);
    const int tid = threadIdx.x;
    const int wid = tid >> 5, lane = tid & 31;
    const int b = blockIdx.z;
    const int bm = blockIdx.y * 128;
    const int bn = blockIdx.x * 128;
    const int wm = wid & 1, wn = wid >> 1;

    const __half* A = A_ + (size_t)b * aB + (size_t)bm * CCH;
    const __half* B = B_ + (size_t)b * bB + (size_t)bn * CCH;

    float acc[4][4][4];
    #pragma unroll
    for (int mi = 0; mi < 4; mi++)
        #pragma unroll
        for (int ni = 0; ni < 4; ni++)
            #pragma unroll
            for (int r = 0; r < 4; r++) acc[mi][ni][r] = 0.f;

    const int g = lane >> 3;
    const int lrow = (g & 1) * 8 + (lane & 7);
    const int lkb  = (g >> 1) * 16;

    auto load_stage = [&](int ks, int buf) {
        const uint32_t base = sb + buf * GT_STAGE;
        const int k0 = ks * 64;
        #pragma unroll
        for (int u = 0; u < 4; u++) {
            int idx = tid + u * 256;
            int row = idx >> 3, c = idx & 7;
            uint32_t so = base + row * GT_ROW + c * 16;
            size_t go = (size_t)row * CCH + k0 + c * 8;
            cp16(so,           A + go);
            cp16(so + GT_TILE, B + go);
        }
    };

    load_stage(0, 0);
    asm volatile("cp.async.commit_group;" ::: "memory");

    const int ksteps = CCH / 64;
    for (int ks = 0; ks < ksteps; ks++) {
        const int buf = ks & 1;
        if (ks + 1 < ksteps) {
            load_stage(ks + 1, buf ^ 1);
            asm volatile("cp.async.commit_group;" ::: "memory");
            asm volatile("cp.async.wait_group 1;" ::: "memory");
        } else {
            asm volatile("cp.async.wait_group 0;" ::: "memory");
        }
        __syncthreads();

        const uint32_t base = sb + buf * GT_STAGE;
        #pragma unroll
        for (int k16 = 0; k16 < 4; k16++) {
            uint32_t ah[4][4], bh[4][2];
            #pragma unroll
            for (int mi = 0; mi < 4; mi++) {
                uint32_t ra = base + (wm * 64 + mi * 16 + lrow) * GT_ROW + k16 * 32 + lkb;
                ldsm4(ah[mi][0], ah[mi][1], ah[mi][2], ah[mi][3], ra);
            }
            #pragma unroll
            for (int p = 0; p < 2; p++) {
                uint32_t rb = base + GT_TILE + (wn * 32 + p * 16 + lrow) * GT_ROW + k16 * 32 + lkb;
                uint32_t r0, r1, r2, r3;
                ldsm4(r0, r1, r2, r3, rb);
                bh[2*p][0] = r0; bh[2*p+1][0] = r1; bh[2*p][1] = r2; bh[2*p+1][1] = r3;
            }
            #pragma unroll
            for (int mi = 0; mi < 4; mi++)
                #pragma unroll
                for (int ni = 0; ni < 4; ni++)
                    mma_f16(acc[mi][ni], ah[mi], bh[ni]);
        }
        __syncthreads();
    }

    #pragma unroll
    for (int mi = 0; mi < 4; mi++) {
        int r0 = bm + wm * 64 + mi * 16 + (lane >> 2);
        #pragma unroll
        for (int ni = 0; ni < 4; ni++) {
            int col = bn + wn * 32 + ni * 8 + (lane & 3) * 2;
            #pragma unroll
            for (int half = 0; half < 2; half++) {
                int row = r0 + half * 8;
                float v0 = acc[mi][ni][half * 2 + 0];
                float v1 = acc[mi][ni][half * 2 + 1];
                if (EPI == 0) {
                    v0 += bias[col]; v1 += bias[col + 1];
                    *(__half2*)(outh + (size_t)b * oB + (size_t)row * ostr + col) =
                        __floats2half2_rn(v0, v1);
                } else {
                    size_t o = (size_t)b * oB + (size_t)row * ostr + col;
                    float bv = bias[row];
                    float2 r = *(const float2*)(resid + o);
                    *(float2*)(outf + o) = make_float2(v0 + bv + r.x, v1 + bv + r.y);
                }
            }
        }
    }
}

// ---------------- fused flash attention (KB=64, 2-stage, fp16x2 softmax) ----------------
#define QR 128
#define KB 64
#define QSTRIDE 528
#define Q_BYTES (QR * QSTRIDE)            // 67584
#define KV_ROW 528
#define K_BYTES (KB * KV_ROW)             // 33792
#define FA_STAGE (2 * K_BYTES)            // 67584
#define FA_BAR (Q_BYTES + 2 * FA_STAGE)   // 202752
#define FA_SMEM (FA_BAR + 64)

__global__ __launch_bounds__(288, 1)
void flash_attn(const __half* __restrict__ qkvt) {
    extern __shared__ char smem[];
    const uint32_t sb = smem_u32(smem);
    const int tid = threadIdx.x;
    const int wid = tid >> 5, lane = tid & 31;
    const int b = blockIdx.y;
    const int bm = blockIdx.x * QR;
    const __half* base = qkvt + (size_t)b * HW * NQKV;

    const uint32_t sQ = sb;
    const uint32_t sK0 = sb + Q_BYTES;
    const uint32_t BARS = sb + FA_BAR;

    if (tid == 0) {
        MBAR_INIT(BARS + 0, 32u);
        MBAR_INIT(BARS + 8, 32u);
        MBAR_INIT(BARS + 16, 8u);
        MBAR_INIT(BARS + 24, 8u);
    }
    for (int u = tid; u < 4096; u += 288) {
        int row = u >> 5, c = u & 31;
        cp16(sQ + row * QSTRIDE + c * 16, base + (size_t)(bm + row) * NQKV + c * 8);
    }
    asm volatile("cp.async.commit_group;" ::: "memory");
    asm volatile("cp.async.wait_group 0;" ::: "memory");
    __syncthreads();

    const int NITER = HW / KB;

    if (wid == 8) {
        for (int ks = 0; ks < NITER; ks++) {
            int buf = ks & 1;
            if (ks >= 2) {
                int par = ((ks >> 1) - 1) & 1;
                MBAR_WAIT(BARS + 16 + buf * 8, par);
            }
            uint32_t st = sK0 + buf * FA_STAGE;
            const __half* gk = base + (size_t)(ks * KB) * NQKV;
            for (int u = lane; u < 2048; u += 32) {
                int row = u >> 5, c = u & 31;
                const __half* gp = gk + (size_t)row * NQKV + c * 8;
                cp16(st + row * KV_ROW + c * 16,           gp + 256);   // K
                cp16(st + K_BYTES + row * KV_ROW + c * 16, gp + 512);   // V
            }
            asm volatile("cp.async.mbarrier.arrive.noinc.shared.b64 [%0];"
                         :: "r"(BARS + buf * 8) : "memory");
        }
        return;
    }

    float O[32][4];
    #pragma unroll
    for (int nt = 0; nt < 32; nt++)
        #pragma unroll
        for (int r = 0; r < 4; r++) O[nt][r] = 0.f;
    float m0 = -1e30f, m1 = -1e30f, l0 = 0.f, l1 = 0.f;

    const int g = lane >> 3;
    const int lrow = (g & 1) * 8 + (lane & 7);
    const int lkb = (g >> 1) * 16;
    const float c1 = 0.0625f * 1.44269504f;   // log2(e)/16

    for (int it = 0; it < NITER; it++) {
        const int buf = it & 1;
        MBAR_WAIT(BARS + buf * 8, (it >> 1) & 1);
        const uint32_t sK = sK0 + buf * FA_STAGE;
        const uint32_t sV = sK + K_BYTES;

        // ---- S = Q K^T ----
        float S[8][4];
        #pragma unroll
        for (int nt = 0; nt < 8; nt++)
            #pragma unroll
            for (int r = 0; r < 4; r++) S[nt][r] = 0.f;

        #pragma unroll
        for (int k16 = 0; k16 < 16; k16++) {
            uint32_t a[4];
            ldsm4(a[0], a[1], a[2], a[3],
                  sQ + (wid * 16 + lrow) * QSTRIDE + k16 * 32 + lkb);
            uint32_t kb[8][2];
            #pragma unroll
            for (int p = 0; p < 4; p++) {
                uint32_t r0, r1, r2, r3;
                ldsm4(r0, r1, r2, r3, sK + (p * 16 + lrow) * KV_ROW + k16 * 32 + lkb);
                kb[2*p][0] = r0; kb[2*p+1][0] = r1;
                kb[2*p][1] = r2; kb[2*p+1][1] = r3;
            }
            #pragma unroll
            for (int nt = 0; nt < 8; nt++)
                mma_f16(S[nt], a, kb[nt]);
        }

        // ---- online softmax (fp16x2 exp) ----
        float mx0 = -1e30f, mx1 = -1e30f;
        #pragma unroll
        for (int nt = 0; nt < 8; nt++) {
            mx0 = fmaxf(mx0, fmaxf(S[nt][0], S[nt][1]));
            mx1 = fmaxf(mx1, fmaxf(S[nt][2], S[nt][3]));
        }
        mx0 = fmaxf(mx0, __shfl_xor_sync(0xffffffffu, mx0, 1));
        mx0 = fmaxf(mx0, __shfl_xor_sync(0xffffffffu, mx0, 2));
        mx1 = fmaxf(mx1, __shfl_xor_sync(0xffffffffu, mx1, 1));
        mx1 = fmaxf(mx1, __shfl_xor_sync(0xffffffffu, mx1, 2));
        float nm0 = fmaxf(m0, mx0), nm1 = fmaxf(m1, mx1);
        float a0 = exp2f((m0 - nm0) * c1), a1 = exp2f((m1 - nm1) * c1);
        m0 = nm0; m1 = nm1;
        float bb0 = -m0 * c1, bb1 = -m1 * c1;

        uint32_t P0[8], P1[8];
        __half2 hs0 = __float2half2_rn(0.f), hs1 = __float2half2_rn(0.f);
        #pragma unroll
        for (int nt = 0; nt < 8; nt++) {
            float e00 = fmaf(S[nt][0], c1, bb0);
            float e01 = fmaf(S[nt][1], c1, bb0);
            float e10 = fmaf(S[nt][2], c1, bb1);
            float e11 = fmaf(S[nt][3], c1, bb1);
            __half2 p0 = h2exp2(__floats2half2_rn(e00, e01));
            __half2 p1 = h2exp2(__floats2half2_rn(e10, e11));
            P0[nt] = *(uint32_t*)&p0;
            P1[nt] = *(uint32_t*)&p1;
            hs0 = __hadd2(hs0, p0);
            hs1 = __hadd2(hs1, p1);
        }
        float rs0 = __low2float(hs0) + __high2float(hs0);
        float rs1 = __low2float(hs1) + __high2float(hs1);

        if (!__all_sync(0xffffffffu, (a0 == 1.f) && (a1 == 1.f))) {
            #pragma unroll
            for (int nt = 0; nt < 32; nt++) {
                O[nt][0] *= a0; O[nt][1] *= a0;
                O[nt][2] *= a1; O[nt][3] *= a1;
            }
            l0 *= a0; l1 *= a1;
        }
        l0 += rs0; l1 += rs1;

        // ---- O += P V ----
        #pragma unroll
        for (int k16 = 0; k16 < 4; k16++) {
            uint32_t pa[4];
            pa[0] = P0[2 * k16];
            pa[1] = P1[2 * k16];
            pa[2] = P0[2 * k16 + 1];
            pa[3] = P1[2 * k16 + 1];
            int krl = k16 * 16 + (g & 1) * 8 + (lane & 7);
            #pragma unroll
            for (int p = 0; p < 16; p++) {
                int ncl = p * 16 + (g >> 1) * 8;
                uint32_t r0, r1, r2, r3;
                ldsm4t(r0, r1, r2, r3, sV + krl * KV_ROW + ncl * 2);
                uint32_t vb0[2] = {r0, r1};
                uint32_t vb1[2] = {r2, r3};
                mma_f16(O[2*p],     pa, vb0);
                mma_f16(O[2*p + 1], pa, vb1);
            }
        }
        if (lane == 0) MBAR_ARRIVE(BARS + 16 + buf * 8);
    }

    // ---- epilogue: normalize -> fp16 attn ----
    l0 += __shfl_xor_sync(0xffffffffu, l0, 1);
    l0 += __shfl_xor_sync(0xffffffffu, l0, 2);
    l1 += __shfl_xor_sync(0xffffffffu, l1, 1);
    l1 += __shfl_xor_sync(0xffffffffu, l1, 2);
    float inv0 = 1.f / l0, inv1 = 1.f / l1;

    __half* oa = g_at16 + (size_t)b * HW * CCH;
    int row0 = bm + wid * 16 + (lane >> 2);
    #pragma unroll
    for (int nt = 0; nt < 32; nt++) {
        int col = nt * 8 + (lane & 3) * 2;
        *(__half2*)(oa + (size_t)row0 * CCH + col) =
            __floats2half2_rn(O[nt][0] * inv0, O[nt][1] * inv0);
        *(__half2*)(oa + (size_t)(row0 + 8) * CCH + col) =
            __floats2half2_rn(O[nt][2] * inv1, O[nt][3] * inv1);
    }
}

// ---------------- launch ----------------
extern "C" void kernel_launch(void* const* d_in, const int* in_sizes, int n_in,
                              void* d_out, int out_size) {
    const float* x     = (const float*)d_in[0];
    const float* gnw   = (const float*)d_in[1];
    const float* gnb   = (const float*)d_in[2];
    const float* qkvw  = (const float*)d_in[3];
    const float* qkvb  = (const float*)d_in[4];
    const float* projw = (const float*)d_in[5];
    const float* projb = (const float*)d_in[6];
    float* out = (float*)d_out;

    __half *qkvt, *xn16, *wq16, *wp16, *at16;
    cudaGetSymbolAddress((void**)&qkvt, g_qkvt);
    cudaGetSymbolAddress((void**)&xn16, g_xn16);
    cudaGetSymbolAddress((void**)&wq16, g_wq16);
    cudaGetSymbolAddress((void**)&wp16, g_wp16);
    cudaGetSymbolAddress((void**)&at16, g_at16);

    cudaFuncSetAttribute((const void*)hmma_f16gemm<0>,
                         cudaFuncAttributeMaxDynamicSharedMemorySize, GT_SMEM);
    cudaFuncSetAttribute((const void*)hmma_f16gemm<1>,
                         cudaFuncAttributeMaxDynamicSharedMemorySize, GT_SMEM);
    cudaFuncSetAttribute((const void*)flash_attn,
                         cudaFuncAttributeMaxDynamicSharedMemorySize, FA_SMEM);

    // 1. GroupNorm stats + weight fp16 conversion (fused)
    const int wblocks = (NQKV * CCH + CCH * CCH + 255) / 256;
    gn_stats_w16<<<BATCH * NGROUPS + wblocks, 256>>>(x, qkvw, projw);
    gn_apply_t<<<dim3(HW / 32, CCH / 32, BATCH), dim3(32, 8)>>>(x, gnw, gnb);

    // 2. qkv fp16 GEMM
    hmma_f16gemm<0><<<dim3(NQKV / 128, HW / 128, BATCH), 256, GT_SMEM>>>(
        xn16, wq16, qkvb, qkvt, nullptr, nullptr,
        (size_t)HW * CCH, 0, NQKV, (size_t)HW * NQKV);

    // 3-5. fused flash attention
    flash_attn<<<dim3(HW / QR, BATCH), 288, FA_SMEM>>>(qkvt);

    // 6. proj fp16
    hmma_f16gemm<1><<<dim3(HW / 128, CCH / 128, BATCH), 256, GT_SMEM>>>(
        wp16, at16, projb, nullptr, out, x,
        0, (size_t)HW * CCH, HW, (size_t)CCH * HW);
}